// round 1
// baseline (speedup 1.0000x reference)
#include <cuda_runtime.h>
#include <math.h>

// ---------------- problem constants ----------------
static constexpr int F   = 15;
static constexpr int H   = 128;
static constexpr int L   = 12;
static constexpr int NB  = 16;
static constexpr int M   = 3 * NB - 1;   // 47
static constexpr int FM  = F * M;        // 705
static constexpr int B   = 65536;

static constexpr float TAIL = 3.0f;
static constexpr float MINP = 0.001f;    // MIN_W == MIN_H == MIN_D

// ---------------- kernel tiling ----------------
static constexpr int TS   = 64;    // samples per block
static constexpr int NT   = 256;   // threads per block
static constexpr int HS   = 129;   // smem stride for h/t (pad to break conflicts)
static constexpr int WSTR = 144;   // smem stride for weight/raw chunks (>=141)

static constexpr int SMEM_FLOATS =
    TS * HS        // hs
  + TS * HS        // ts
  + H * WSTR       // ws  (weight chunk [j][i])
  + TS * WSTR      // raw (spline params chunk)
  + TS * 16        // xs  (current x, reversed)
  + TS * 3;        // lds4 (per (sample,feature-lane) logdet partials)
static constexpr int SMEM_BYTES = SMEM_FLOATS * 4;  // 181,504 B

// ---------------- device scratch (no allocations allowed) ----------------
__device__ float g_WiT[L * F * H];       // masked+transposed W_init   [l][f][i]
__device__ float g_WrT[L * 4 * H * H];   // masked+transposed W_res    [l][m][j][i]
__device__ float g_WoT[L * H * FM];      // masked+transposed W_out    [l][j][o]
__device__ float g_x  [(size_t)B * F];   // flow state between layers
__device__ float g_ld [B];               // logdet accumulator between layers

// ---------------- premask + transpose ----------------
__global__ void premask_kernel(const float* __restrict__ Wi,
                               const float* __restrict__ Wr,
                               const float* __restrict__ Wo)
{
    int tid = blockIdx.x * blockDim.x + threadIdx.x;
    int nth = gridDim.x * blockDim.x;

    // W_init: (L,H,F) -> [l][f][i], mask m_init[i][f] = (i%14 >= f)
    for (int idx = tid; idx < L * F * H; idx += nth) {
        int l = idx / (F * H);
        int r = idx % (F * H);
        int f = r / H;
        int i = r % H;
        float mk = ((i % (F - 1)) >= f) ? 1.0f : 0.0f;
        g_WiT[idx] = Wi[(l * H + i) * F + f] * mk;
    }
    // W_res: (L,2,2,H,H) -> [l*4+m][j][i], mask m_h[i][j] = (i%14 >= j%14)
    for (int idx = tid; idx < L * 4 * H * H; idx += nth) {
        int lm = idx / (H * H);
        int r  = idx % (H * H);
        int j  = r / H;
        int i  = r % H;
        float mk = ((i % (F - 1)) >= (j % (F - 1))) ? 1.0f : 0.0f;
        g_WrT[idx] = Wr[((size_t)lm * H + i) * H + j] * mk;
    }
    // W_out: (L,FM,H) -> [l][j][o], mask m_out[o][j] = (o/47 > j%14)
    for (int idx = tid; idx < L * H * FM; idx += nth) {
        int l = idx / (H * FM);
        int r = idx % (H * FM);
        int j = r / FM;
        int o = r % FM;
        float mk = ((o / M) > (j % (F - 1))) ? 1.0f : 0.0f;
        g_WoT[idx] = Wo[((size_t)l * FM + o) * H + j] * mk;
    }
}

// ---------------- helpers ----------------
__device__ __forceinline__ float softplusf(float v) {
    // log(1+exp(v)) = max(v,0) + log1p(exp(-|v|))
    return fmaxf(v, 0.0f) + log1pf(expf(-fabsf(v)));
}

// C[s][c] (=|+=) bias[c] + sum_j act(A[s][j]) * W[j][c]
// W is smem with row stride WSTR. NC <= WSTR. K arbitrary.
template <bool RELU, bool ACCUM>
__device__ __forceinline__ void gemm_smem(const float* __restrict__ A, int lda,
                                          const float* __restrict__ W,
                                          float*       __restrict__ C, int ldc,
                                          const float* __restrict__ bias,
                                          int K, int NC)
{
    const int NCG = (NC + 7) / 8;
    for (int t = threadIdx.x; t < 16 * NCG; t += NT) {
        int sg = t / NCG;
        int cg = t % NCG;
        int s0 = sg * 4;
        int c0 = cg * 8;

        float acc[4][8];
        #pragma unroll
        for (int cc = 0; cc < 8; cc++) {
            int c = c0 + cc;
            float bv = (c < NC) ? bias[c] : 0.0f;
            #pragma unroll
            for (int k = 0; k < 4; k++) acc[k][cc] = bv;
        }

        for (int j = 0; j < K; j++) {
            const float* wrow = W + j * WSTR + c0;
            float4 w0 = *(const float4*)(wrow);
            float4 w1 = *(const float4*)(wrow + 4);
            #pragma unroll
            for (int k = 0; k < 4; k++) {
                float a = A[(s0 + k) * lda + j];
                if (RELU) a = fmaxf(a, 0.0f);
                acc[k][0] = fmaf(a, w0.x, acc[k][0]);
                acc[k][1] = fmaf(a, w0.y, acc[k][1]);
                acc[k][2] = fmaf(a, w0.z, acc[k][2]);
                acc[k][3] = fmaf(a, w0.w, acc[k][3]);
                acc[k][4] = fmaf(a, w1.x, acc[k][4]);
                acc[k][5] = fmaf(a, w1.y, acc[k][5]);
                acc[k][6] = fmaf(a, w1.z, acc[k][6]);
                acc[k][7] = fmaf(a, w1.w, acc[k][7]);
            }
        }

        #pragma unroll
        for (int k = 0; k < 4; k++) {
            #pragma unroll
            for (int cc = 0; cc < 8; cc++) {
                int c = c0 + cc;
                if (c < NC) {
                    float* cp = C + (s0 + k) * ldc + c;
                    if (ACCUM) *cp += acc[k][cc];
                    else       *cp  = acc[k][cc];
                }
            }
        }
    }
}

// ---------------- one flow layer ----------------
__global__ void __launch_bounds__(NT, 1)
layer_kernel(const float* __restrict__ x0,      // original input x (layer 0 only)
             float* __restrict__ outz,          // d_out z region (layer L-1 only)
             float* __restrict__ outld,         // d_out logdet region (layer L-1 only)
             int layer,
             const float* __restrict__ b_init,
             const float* __restrict__ b_res,
             const float* __restrict__ b_out)
{
    extern __shared__ float sm[];
    float* hs   = sm;                       // [TS][HS]
    float* ts   = hs   + TS * HS;           // [TS][HS]
    float* ws   = ts   + TS * HS;           // [H][WSTR]
    float* raw  = ws   + H * WSTR;          // [TS][WSTR]
    float* xs   = raw  + TS * WSTR;         // [TS][16]
    float* lds4 = xs   + TS * 16;           // [TS*3]

    const int tid = threadIdx.x;
    const int gs0 = blockIdx.x * TS;

    const float* x_in  = (layer == 0)     ? x0   : g_x;
    float*       x_out = (layer == L - 1) ? outz : g_x;

    // load this block's samples, reversed along features
    for (int e = tid; e < TS * F; e += NT) {
        int s = e / F, f = e % F;
        xs[s * 16 + f] = x_in[(size_t)(gs0 + s) * F + (F - 1 - f)];
    }

    // ---- init GEMM: h = xs @ WiT + b_init ----
    const float* Wi = g_WiT + (size_t)layer * F * H;
    for (int e = tid; e < F * H; e += NT)
        ws[(e / H) * WSTR + (e % H)] = Wi[e];
    __syncthreads();
    gemm_smem<false, false>(xs, 16, ws, hs, HS, b_init + layer * H, F, H);
    __syncthreads();

    // ---- two residual blocks ----
    for (int blk = 0; blk < 2; blk++) {
        const float* Wa = g_WrT + ((size_t)layer * 4 + blk * 2) * H * H;

        for (int e4 = tid; e4 < H * H / 4; e4 += NT) {
            int j = e4 >> 5, i4 = e4 & 31;
            *(float4*)(ws + j * WSTR + i4 * 4) = *(const float4*)(Wa + j * H + i4 * 4);
        }
        __syncthreads();
        gemm_smem<true, false>(hs, HS, ws, ts, HS,
                               b_res + ((layer * 2 + blk) * 2 + 0) * H, H, H);
        __syncthreads();

        const float* Wb = Wa + H * H;
        for (int e4 = tid; e4 < H * H / 4; e4 += NT) {
            int j = e4 >> 5, i4 = e4 & 31;
            *(float4*)(ws + j * WSTR + i4 * 4) = *(const float4*)(Wb + j * H + i4 * 4);
        }
        __syncthreads();
        gemm_smem<true, true>(ts, HS, ws, hs, HS,
                              b_res + ((layer * 2 + blk) * 2 + 1) * H, H, H);
        __syncthreads();
    }

    // ---- output GEMM + spline, 3 features (141 cols) at a time ----
    const float* Wo = g_WoT + (size_t)layer * H * FM;
    float lad_acc = 0.0f;
    const int sid  = tid / 3;
    const int flid = tid % 3;

    for (int fb = 0; fb < F; fb += 3) {
        int base = fb * M;
        int nc   = 3 * M;   // 141

        for (int e = tid; e < H * WSTR; e += NT) {
            int j = e / WSTR, c = e % WSTR;
            ws[e] = (c < nc) ? Wo[(size_t)j * FM + base + c] : 0.0f;
        }
        __syncthreads();

        gemm_smem<false, false>(hs, HS, ws, raw, WSTR,
                                b_out + (size_t)layer * FM + base, H, nc);
        __syncthreads();

        if (tid < TS * 3) {
            const float* p = raw + sid * WSTR + flid * M;
            int   f  = fb + flid;
            float xv = xs[sid * 16 + f];
            float xc = fminf(fmaxf(xv, -TAIL), TAIL);
            bool inside = (xv >= -TAIL) && (xv <= TAIL);

            // ---- widths softmax + knot walk (find bin 'sel') ----
            float mw = -1e30f;
            #pragma unroll
            for (int i = 0; i < NB; i++) mw = fmaxf(mw, p[i]);
            float Sw = 0.0f;
            #pragma unroll
            for (int i = 0; i < NB; i++) Sw += expf(p[i] - mw);
            float invw = (1.0f - NB * MINP) / Sw;

            float cum = 0.0f;
            int   sel = 0;
            float lo = -TAIL, hi = TAIL;
            bool  gotHi = false;
            #pragma unroll
            for (int i = 0; i < NB; i++) {
                float wi = MINP + expf(p[i] - mw) * invw;
                cum += wi;
                float kv = (i == NB - 1) ? TAIL : fmaf(2.0f * TAIL, cum, -TAIL);
                if (i < NB - 1 && xc >= kv) { sel = i + 1; lo = kv; }
                if (!gotHi && xc < kv)      { hi = kv; gotHi = true; }
            }
            float w_bin = hi - lo;

            // ---- heights softmax + knot walk (gather at sel, sel+1) ----
            float mh = -1e30f;
            #pragma unroll
            for (int i = 0; i < NB; i++) mh = fmaxf(mh, p[NB + i]);
            float Sh = 0.0f;
            #pragma unroll
            for (int i = 0; i < NB; i++) Sh += expf(p[NB + i] - mh);
            float invh = (1.0f - NB * MINP) / Sh;

            float cumh = 0.0f;
            float chlo = -TAIL, chhi = TAIL;
            #pragma unroll
            for (int i = 0; i < NB; i++) {
                float hv = MINP + expf(p[NB + i] - mh) * invh;
                cumh += hv;
                float kv = (i == NB - 1) ? TAIL : fmaf(2.0f * TAIL, cumh, -TAIL);
                if (i + 1 == sel)     chlo = kv;
                if (i + 1 == sel + 1) chhi = kv;
            }
            float h_bin = chhi - chlo;

            // ---- derivatives (padded ends are exactly 1.0) ----
            float d0 = (sel == 0)      ? 1.0f : (MINP + softplusf(p[2 * NB + sel - 1]));
            float d1 = (sel == NB - 1) ? 1.0f : (MINP + softplusf(p[2 * NB + sel]));

            // ---- rational quadratic ----
            float delta = h_bin / w_bin;
            float theta = (xc - lo) / w_bin;
            float omt   = 1.0f - theta;
            float tomt  = theta * omt;
            float th2   = theta * theta;
            float num   = h_bin * (delta * th2 + d0 * tomt);
            float den   = delta + (d0 + d1 - 2.0f * delta) * tomt;
            float y     = chlo + num / den;
            float dnum  = delta * delta * (d1 * th2 + 2.0f * delta * tomt + d0 * omt * omt);
            float lad   = logf(dnum) - 2.0f * logf(den);

            if (!inside) { y = xv; lad = 0.0f; }
            xs[sid * 16 + f] = y;
            lad_acc += lad;
        }
        __syncthreads();
    }

    if (tid < TS * 3) lds4[tid] = lad_acc;
    __syncthreads();

    // ---- write new state / final outputs ----
    for (int e = tid; e < TS * F; e += NT) {
        int s = e / F, f = e % F;
        x_out[(size_t)(gs0 + s) * F + f] = xs[s * 16 + f];
    }
    if (tid < TS) {
        int   g    = gs0 + tid;
        float prev = (layer == 0) ? 0.0f : g_ld[g];
        float v    = prev + lds4[tid * 3] + lds4[tid * 3 + 1] + lds4[tid * 3 + 2];
        if (layer == L - 1) outld[g] = v;
        else                g_ld[g]  = v;
    }
}

// ---------------- launch ----------------
extern "C" void kernel_launch(void* const* d_in, const int* in_sizes, int n_in,
                              void* d_out, int out_size)
{
    (void)in_sizes; (void)n_in; (void)out_size;
    const float* x  = (const float*)d_in[0];
    const float* Wi = (const float*)d_in[1];
    const float* bi = (const float*)d_in[2];
    const float* Wr = (const float*)d_in[3];
    const float* br = (const float*)d_in[4];
    const float* Wo = (const float*)d_in[5];
    const float* bo = (const float*)d_in[6];
    float* outz  = (float*)d_out;
    float* outld = (float*)d_out + (size_t)B * F;

    cudaFuncSetAttribute(layer_kernel,
                         cudaFuncAttributeMaxDynamicSharedMemorySize, SMEM_BYTES);

    premask_kernel<<<512, 256>>>(Wi, Wr, Wo);

    for (int l = 0; l < L; l++) {
        layer_kernel<<<B / TS, NT, SMEM_BYTES>>>(x, outz, outld, l, bi, br, bo);
    }
}

// round 2
// speedup vs baseline: 1.2135x; 1.2135x over previous
#include <cuda_runtime.h>
#include <math.h>

// ---------------- problem constants ----------------
static constexpr int F   = 15;
static constexpr int H   = 128;
static constexpr int L   = 12;
static constexpr int NB  = 16;
static constexpr int M   = 3 * NB - 1;   // 47
static constexpr int FM  = F * M;        // 705
static constexpr int B   = 65536;

static constexpr float TAIL = 3.0f;
static constexpr float MINP = 0.001f;    // MIN_W == MIN_H == MIN_D

// ---------------- kernel tiling ----------------
static constexpr int TS   = 64;    // samples per block
static constexpr int NT   = 256;   // threads per block
static constexpr int HS   = 129;   // smem stride for h/t
static constexpr int WSTR = 144;   // smem stride for weight/raw chunks (>=141)
static constexpr int KH   = 64;    // k-half for weight staging

// smem layout (floats):
//   hs   [TS][HS]          8256
//   buf2 [TS][WSTR]        9216   (ts with stride HS during residual; raw with stride WSTR in output)
//   ws   [KH][WSTR]        9216   (k-half weight chunk)
//   xs   [TS][16]          1024
//   lds  [TS*3]             192
static constexpr int SMEM_FLOATS = TS*HS + TS*WSTR + KH*WSTR + TS*16 + TS*3;
static constexpr int SMEM_BYTES  = SMEM_FLOATS * 4;   // 111,616 B -> 2 blocks/SM

// ---------------- device scratch ----------------
__device__ float g_WiT[L * F * H];       // masked+transposed W_init   [l][f][i]
__device__ float g_WrT[L * 4 * H * H];   // masked+transposed W_res    [l][m][j][i]
__device__ float g_WoT[L * H * FM];      // masked+transposed W_out    [l][j][o]
__device__ float g_x  [(size_t)B * F];   // flow state between layers
__device__ float g_ld [B];               // logdet accumulator between layers

// ---------------- premask + transpose ----------------
__global__ void premask_kernel(const float* __restrict__ Wi,
                               const float* __restrict__ Wr,
                               const float* __restrict__ Wo)
{
    int tid = blockIdx.x * blockDim.x + threadIdx.x;
    int nth = gridDim.x * blockDim.x;

    for (int idx = tid; idx < L * F * H; idx += nth) {
        int l = idx / (F * H);
        int r = idx % (F * H);
        int f = r / H;
        int i = r % H;
        float mk = ((i % (F - 1)) >= f) ? 1.0f : 0.0f;
        g_WiT[idx] = Wi[(l * H + i) * F + f] * mk;
    }
    for (int idx = tid; idx < L * 4 * H * H; idx += nth) {
        int lm = idx / (H * H);
        int r  = idx % (H * H);
        int j  = r / H;
        int i  = r % H;
        float mk = ((i % (F - 1)) >= (j % (F - 1))) ? 1.0f : 0.0f;
        g_WrT[idx] = Wr[((size_t)lm * H + i) * H + j] * mk;
    }
    for (int idx = tid; idx < L * H * FM; idx += nth) {
        int l = idx / (H * FM);
        int r = idx % (H * FM);
        int j = r / FM;
        int o = r % FM;
        float mk = ((o / M) > (j % (F - 1))) ? 1.0f : 0.0f;
        g_WoT[idx] = Wo[((size_t)l * FM + o) * H + j] * mk;
    }
}

// ---------------- packed fp32 helpers ----------------
typedef unsigned long long ull;

__device__ __forceinline__ ull pack2(float lo, float hi) {
    ull r; asm("mov.b64 %0, {%1,%2};" : "=l"(r) : "f"(lo), "f"(hi)); return r;
}
__device__ __forceinline__ void unpack2(ull v, float& lo, float& hi) {
    asm("mov.b64 {%0,%1}, %2;" : "=f"(lo), "=f"(hi) : "l"(v));
}
__device__ __forceinline__ ull ffma2(ull a, ull b, ull c) {
    ull d; asm("fma.rn.f32x2 %0, %1, %2, %3;" : "=l"(d) : "l"(a), "l"(b), "l"(c)); return d;
}

__device__ __forceinline__ float softplusf(float v) {
    return fmaxf(v, 0.0f) + log1pf(expf(-fabsf(v)));
}

// C[s][c] (=|+=) [bias[c]] + sum_{j<K} act(A[s][j]) * W[j][c]
// W in smem, row stride WSTR. Packed f32x2 over column pairs.
template <bool RELU, bool ACCUM, bool BIAS>
__device__ __forceinline__ void gemm2(const float* __restrict__ A, int lda,
                                      const float* __restrict__ W,
                                      float*       __restrict__ C, int ldc,
                                      const float* __restrict__ bias,
                                      int K, int NC)
{
    const int NCG = (NC + 7) / 8;
    for (int t = threadIdx.x; t < 16 * NCG; t += NT) {
        const int s0 = (t / NCG) * 4;
        const int c0 = (t % NCG) * 8;

        ull acc[4][4];
        {
            ull bv[4];
            #pragma unroll
            for (int i = 0; i < 4; i++) {
                float lo = 0.0f, hi = 0.0f;
                if (BIAS) {
                    int c = c0 + 2 * i;
                    if (c     < NC) lo = bias[c];
                    if (c + 1 < NC) hi = bias[c + 1];
                }
                bv[i] = pack2(lo, hi);
            }
            #pragma unroll
            for (int k = 0; k < 4; k++)
                #pragma unroll
                for (int i = 0; i < 4; i++) acc[k][i] = bv[i];
        }

        const float* a0 = A + (s0 + 0) * lda;
        const float* a1 = A + (s0 + 1) * lda;
        const float* a2 = A + (s0 + 2) * lda;
        const float* a3 = A + (s0 + 3) * lda;
        const float* wrow = W + c0;

        #pragma unroll 4
        for (int j = 0; j < K; j++) {
            ulonglong2 w01 = *(const ulonglong2*)(wrow);
            ulonglong2 w23 = *(const ulonglong2*)(wrow + 4);
            wrow += WSTR;

            float v0 = a0[j], v1 = a1[j], v2 = a2[j], v3 = a3[j];
            if (RELU) {
                v0 = fmaxf(v0, 0.0f); v1 = fmaxf(v1, 0.0f);
                v2 = fmaxf(v2, 0.0f); v3 = fmaxf(v3, 0.0f);
            }
            ull p0 = pack2(v0, v0), p1 = pack2(v1, v1);
            ull p2 = pack2(v2, v2), p3 = pack2(v3, v3);

            acc[0][0] = ffma2(p0, w01.x, acc[0][0]);
            acc[0][1] = ffma2(p0, w01.y, acc[0][1]);
            acc[0][2] = ffma2(p0, w23.x, acc[0][2]);
            acc[0][3] = ffma2(p0, w23.y, acc[0][3]);
            acc[1][0] = ffma2(p1, w01.x, acc[1][0]);
            acc[1][1] = ffma2(p1, w01.y, acc[1][1]);
            acc[1][2] = ffma2(p1, w23.x, acc[1][2]);
            acc[1][3] = ffma2(p1, w23.y, acc[1][3]);
            acc[2][0] = ffma2(p2, w01.x, acc[2][0]);
            acc[2][1] = ffma2(p2, w01.y, acc[2][1]);
            acc[2][2] = ffma2(p2, w23.x, acc[2][2]);
            acc[2][3] = ffma2(p2, w23.y, acc[2][3]);
            acc[3][0] = ffma2(p3, w01.x, acc[3][0]);
            acc[3][1] = ffma2(p3, w01.y, acc[3][1]);
            acc[3][2] = ffma2(p3, w23.x, acc[3][2]);
            acc[3][3] = ffma2(p3, w23.y, acc[3][3]);
        }

        #pragma unroll
        for (int k = 0; k < 4; k++) {
            float* cp = C + (s0 + k) * ldc + c0;
            #pragma unroll
            for (int i = 0; i < 4; i++) {
                float lo, hi;
                unpack2(acc[k][i], lo, hi);
                int c = c0 + 2 * i;
                if (c < NC)     { if (ACCUM) cp[2*i]   += lo; else cp[2*i]   = lo; }
                if (c + 1 < NC) { if (ACCUM) cp[2*i+1] += hi; else cp[2*i+1] = hi; }
            }
        }
    }
}

// ---------------- weight staging (k-half) ----------------
__device__ __forceinline__ void stage_res_half(float* __restrict__ ws,
                                               const float* __restrict__ Wsrc,
                                               int j0)
{
    for (int e4 = threadIdx.x; e4 < KH * H / 4; e4 += NT) {
        int j = e4 >> 5, i4 = e4 & 31;
        *(float4*)(ws + j * WSTR + i4 * 4) =
            *(const float4*)(Wsrc + (size_t)(j0 + j) * H + i4 * 4);
    }
}

// ---------------- one flow layer ----------------
__global__ void __launch_bounds__(NT, 2)
layer_kernel(const float* __restrict__ x0,
             float* __restrict__ outz,
             float* __restrict__ outld,
             int layer,
             const float* __restrict__ b_init,
             const float* __restrict__ b_res,
             const float* __restrict__ b_out)
{
    extern __shared__ float sm[];
    float* hs   = sm;                       // [TS][HS]
    float* buf2 = hs   + TS * HS;           // ts ([TS][HS]) / raw ([TS][WSTR])
    float* ws   = buf2 + TS * WSTR;         // [KH][WSTR]
    float* xs   = ws   + KH * WSTR;         // [TS][16]
    float* lds4 = xs   + TS * 16;           // [TS*3]

    const int tid = threadIdx.x;
    const int gs0 = blockIdx.x * TS;

    const float* x_in  = (layer == 0)     ? x0   : g_x;
    float*       x_out = (layer == L - 1) ? outz : g_x;

    for (int e = tid; e < TS * F; e += NT) {
        int s = e / F, f = e % F;
        xs[s * 16 + f] = x_in[(size_t)(gs0 + s) * F + (F - 1 - f)];
    }

    // ---- init GEMM: h = xs @ WiT + b_init (K=15, single pass) ----
    {
        const float* Wi = g_WiT + (size_t)layer * F * H;
        for (int e = tid; e < F * H; e += NT)
            ws[(e / H) * WSTR + (e % H)] = Wi[e];
        __syncthreads();
        gemm2<false, false, true>(xs, 16, ws, hs, HS, b_init + layer * H, F, H);
        __syncthreads();
    }

    // ---- two residual blocks (each GEMM in two k-halves) ----
    for (int blk = 0; blk < 2; blk++) {
        const float* Wa = g_WrT + ((size_t)layer * 4 + blk * 2) * H * H;
        const float* Wb = Wa + H * H;
        const float* ba = b_res + ((layer * 2 + blk) * 2 + 0) * H;
        const float* bb = b_res + ((layer * 2 + blk) * 2 + 1) * H;

        // t = relu(h) @ Wa + ba
        stage_res_half(ws, Wa, 0);
        __syncthreads();
        gemm2<true, false, true>(hs, HS, ws, buf2, HS, ba, KH, H);
        __syncthreads();
        stage_res_half(ws, Wa, KH);
        __syncthreads();
        gemm2<true, true, false>(hs + KH, HS, ws, buf2, HS, nullptr, KH, H);
        __syncthreads();

        // h += relu(t) @ Wb + bb
        stage_res_half(ws, Wb, 0);
        __syncthreads();
        gemm2<true, true, true>(buf2, HS, ws, hs, HS, bb, KH, H);
        __syncthreads();
        stage_res_half(ws, Wb, KH);
        __syncthreads();
        gemm2<true, true, false>(buf2 + KH, HS, ws, hs, HS, nullptr, KH, H);
        __syncthreads();
    }

    // ---- output GEMM + spline, 3 features (141 cols) at a time ----
    const float* Wo = g_WoT + (size_t)layer * H * FM;
    float lad_acc = 0.0f;
    const int sid  = tid / 3;
    const int flid = tid % 3;

    for (int fb = 0; fb < F; fb += 3) {
        const int base = fb * M;
        const int nc   = 3 * M;   // 141

        for (int half = 0; half < 2; half++) {
            const int j0 = half * KH;
            for (int e = tid; e < KH * WSTR; e += NT) {
                int j = e / WSTR, c = e % WSTR;
                ws[e] = (c < nc) ? Wo[(size_t)(j0 + j) * FM + base + c] : 0.0f;
            }
            __syncthreads();
            if (half == 0)
                gemm2<false, false, true>(hs, HS, ws, buf2, WSTR,
                                          b_out + (size_t)layer * FM + base, KH, nc);
            else
                gemm2<false, true, false>(hs + KH, HS, ws, buf2, WSTR,
                                          nullptr, KH, nc);
            __syncthreads();
        }

        if (tid < TS * 3) {
            const float* p = buf2 + sid * WSTR + flid * M;
            int   f  = fb + flid;
            float xv = xs[sid * 16 + f];
            float xc = fminf(fmaxf(xv, -TAIL), TAIL);
            bool inside = (xv >= -TAIL) && (xv <= TAIL);

            // widths softmax + knot walk
            float mw = -1e30f;
            #pragma unroll
            for (int i = 0; i < NB; i++) mw = fmaxf(mw, p[i]);
            float Sw = 0.0f;
            #pragma unroll
            for (int i = 0; i < NB; i++) Sw += expf(p[i] - mw);
            float invw = (1.0f - NB * MINP) / Sw;

            float cum = 0.0f;
            int   sel = 0;
            float lo = -TAIL, hi = TAIL;
            bool  gotHi = false;
            #pragma unroll
            for (int i = 0; i < NB; i++) {
                float wi = MINP + expf(p[i] - mw) * invw;
                cum += wi;
                float kv = (i == NB - 1) ? TAIL : fmaf(2.0f * TAIL, cum, -TAIL);
                if (i < NB - 1 && xc >= kv) { sel = i + 1; lo = kv; }
                if (!gotHi && xc < kv)      { hi = kv; gotHi = true; }
            }
            float w_bin = hi - lo;

            // heights softmax + knot gather
            float mh = -1e30f;
            #pragma unroll
            for (int i = 0; i < NB; i++) mh = fmaxf(mh, p[NB + i]);
            float Sh = 0.0f;
            #pragma unroll
            for (int i = 0; i < NB; i++) Sh += expf(p[NB + i] - mh);
            float invh = (1.0f - NB * MINP) / Sh;

            float cumh = 0.0f;
            float chlo = -TAIL, chhi = TAIL;
            #pragma unroll
            for (int i = 0; i < NB; i++) {
                float hv = MINP + expf(p[NB + i] - mh) * invh;
                cumh += hv;
                float kv = (i == NB - 1) ? TAIL : fmaf(2.0f * TAIL, cumh, -TAIL);
                if (i + 1 == sel)     chlo = kv;
                if (i + 1 == sel + 1) chhi = kv;
            }
            float h_bin = chhi - chlo;

            float d0 = (sel == 0)      ? 1.0f : (MINP + softplusf(p[2 * NB + sel - 1]));
            float d1 = (sel == NB - 1) ? 1.0f : (MINP + softplusf(p[2 * NB + sel]));

            float delta = h_bin / w_bin;
            float theta = (xc - lo) / w_bin;
            float omt   = 1.0f - theta;
            float tomt  = theta * omt;
            float th2   = theta * theta;
            float num   = h_bin * (delta * th2 + d0 * tomt);
            float den   = delta + (d0 + d1 - 2.0f * delta) * tomt;
            float y     = chlo + num / den;
            float dnum  = delta * delta * (d1 * th2 + 2.0f * delta * tomt + d0 * omt * omt);
            float lad   = logf(dnum) - 2.0f * logf(den);

            if (!inside) { y = xv; lad = 0.0f; }
            xs[sid * 16 + f] = y;
            lad_acc += lad;
        }
        __syncthreads();
    }

    if (tid < TS * 3) lds4[tid] = lad_acc;
    __syncthreads();

    for (int e = tid; e < TS * F; e += NT) {
        int s = e / F, f = e % F;
        x_out[(size_t)(gs0 + s) * F + f] = xs[s * 16 + f];
    }
    if (tid < TS) {
        int   g    = gs0 + tid;
        float prev = (layer == 0) ? 0.0f : g_ld[g];
        float v    = prev + lds4[tid * 3] + lds4[tid * 3 + 1] + lds4[tid * 3 + 2];
        if (layer == L - 1) outld[g] = v;
        else                g_ld[g]  = v;
    }
}

// ---------------- launch ----------------
extern "C" void kernel_launch(void* const* d_in, const int* in_sizes, int n_in,
                              void* d_out, int out_size)
{
    (void)in_sizes; (void)n_in; (void)out_size;
    const float* x  = (const float*)d_in[0];
    const float* Wi = (const float*)d_in[1];
    const float* bi = (const float*)d_in[2];
    const float* Wr = (const float*)d_in[3];
    const float* br = (const float*)d_in[4];
    const float* Wo = (const float*)d_in[5];
    const float* bo = (const float*)d_in[6];
    float* outz  = (float*)d_out;
    float* outld = (float*)d_out + (size_t)B * F;

    cudaFuncSetAttribute(layer_kernel,
                         cudaFuncAttributeMaxDynamicSharedMemorySize, SMEM_BYTES);

    premask_kernel<<<512, 256>>>(Wi, Wr, Wo);

    for (int l = 0; l < L; l++) {
        layer_kernel<<<B / TS, NT, SMEM_BYTES>>>(x, outz, outld, l, bi, br, bo);
    }
}

// round 3
// speedup vs baseline: 1.2141x; 1.0005x over previous
#include <cuda_runtime.h>
#include <math.h>

// ---------------- problem constants ----------------
static constexpr int F   = 15;
static constexpr int H   = 128;
static constexpr int L   = 12;
static constexpr int NB  = 16;
static constexpr int M   = 3 * NB - 1;   // 47
static constexpr int FM  = F * M;        // 705
static constexpr int B   = 65536;

static constexpr float TAIL = 3.0f;
static constexpr float MINP = 0.001f;    // MIN_W == MIN_H == MIN_D

// ---------------- kernel tiling ----------------
static constexpr int TS   = 64;    // samples per block
static constexpr int NT   = 256;   // threads per block
static constexpr int HS   = 129;   // smem stride for h/t
static constexpr int WSTR = 144;   // smem stride for weight/raw chunks (>=141)
static constexpr int KH   = 64;    // k-half for weight staging

// smem layout (floats):
//   hs   [TS][HS]          8256
//   buf2 [TS][WSTR]        9216   (ts with stride HS during residual; raw with stride WSTR in output)
//   ws   [KH][WSTR]        9216   (k-half weight chunk)
//   xs   [TS][16]          1024
//   lds  [TS*3]             192
static constexpr int SMEM_FLOATS = TS*HS + TS*WSTR + KH*WSTR + TS*16 + TS*3;
static constexpr int SMEM_BYTES  = SMEM_FLOATS * 4;   // 111,616 B -> 2 blocks/SM

// ---------------- device scratch ----------------
__device__ float g_WiT[L * F * H];       // masked+transposed W_init   [l][f][i]
__device__ float g_WrT[L * 4 * H * H];   // masked+transposed W_res    [l][m][j][i]
__device__ float g_WoT[L * H * FM];      // masked+transposed W_out    [l][j][o]
__device__ float g_x  [(size_t)B * F];   // flow state between layers
__device__ float g_ld [B];               // logdet accumulator between layers

// ---------------- premask + transpose ----------------
__global__ void premask_kernel(const float* __restrict__ Wi,
                               const float* __restrict__ Wr,
                               const float* __restrict__ Wo)
{
    int tid = blockIdx.x * blockDim.x + threadIdx.x;
    int nth = gridDim.x * blockDim.x;

    for (int idx = tid; idx < L * F * H; idx += nth) {
        int l = idx / (F * H);
        int r = idx % (F * H);
        int f = r / H;
        int i = r % H;
        float mk = ((i % (F - 1)) >= f) ? 1.0f : 0.0f;
        g_WiT[idx] = Wi[(l * H + i) * F + f] * mk;
    }
    for (int idx = tid; idx < L * 4 * H * H; idx += nth) {
        int lm = idx / (H * H);
        int r  = idx % (H * H);
        int j  = r / H;
        int i  = r % H;
        float mk = ((i % (F - 1)) >= (j % (F - 1))) ? 1.0f : 0.0f;
        g_WrT[idx] = Wr[((size_t)lm * H + i) * H + j] * mk;
    }
    for (int idx = tid; idx < L * H * FM; idx += nth) {
        int l = idx / (H * FM);
        int r = idx % (H * FM);
        int j = r / FM;
        int o = r % FM;
        float mk = ((o / M) > (j % (F - 1))) ? 1.0f : 0.0f;
        g_WoT[idx] = Wo[((size_t)l * FM + o) * H + j] * mk;
    }
}

// ---------------- packed fp32 helpers ----------------
typedef unsigned long long ull;

__device__ __forceinline__ ull pack2(float lo, float hi) {
    ull r; asm("mov.b64 %0, {%1,%2};" : "=l"(r) : "f"(lo), "f"(hi)); return r;
}
__device__ __forceinline__ void unpack2(ull v, float& lo, float& hi) {
    asm("mov.b64 {%0,%1}, %2;" : "=f"(lo), "=f"(hi) : "l"(v));
}
__device__ __forceinline__ ull ffma2(ull a, ull b, ull c) {
    ull d; asm("fma.rn.f32x2 %0, %1, %2, %3;" : "=l"(d) : "l"(a), "l"(b), "l"(c)); return d;
}

__device__ __forceinline__ float softplusf(float v) {
    return fmaxf(v, 0.0f) + log1pf(expf(-fabsf(v)));
}

// C[s][c] (=|+=) [bias[c]] + sum_{j<K} act(A[s][j]) * W[j][c]
// W in smem, row stride WSTR. Packed f32x2 over column pairs.
template <bool RELU, bool ACCUM, bool BIAS>
__device__ __forceinline__ void gemm2(const float* __restrict__ A, int lda,
                                      const float* __restrict__ W,
                                      float*       __restrict__ C, int ldc,
                                      const float* __restrict__ bias,
                                      int K, int NC)
{
    const int NCG = (NC + 7) / 8;
    for (int t = threadIdx.x; t < 16 * NCG; t += NT) {
        const int s0 = (t / NCG) * 4;
        const int c0 = (t % NCG) * 8;

        ull acc[4][4];
        {
            ull bv[4];
            #pragma unroll
            for (int i = 0; i < 4; i++) {
                float lo = 0.0f, hi = 0.0f;
                if (BIAS) {
                    int c = c0 + 2 * i;
                    if (c     < NC) lo = bias[c];
                    if (c + 1 < NC) hi = bias[c + 1];
                }
                bv[i] = pack2(lo, hi);
            }
            #pragma unroll
            for (int k = 0; k < 4; k++)
                #pragma unroll
                for (int i = 0; i < 4; i++) acc[k][i] = bv[i];
        }

        const float* a0 = A + (s0 + 0) * lda;
        const float* a1 = A + (s0 + 1) * lda;
        const float* a2 = A + (s0 + 2) * lda;
        const float* a3 = A + (s0 + 3) * lda;
        const float* wrow = W + c0;

        #pragma unroll 4
        for (int j = 0; j < K; j++) {
            ulonglong2 w01 = *(const ulonglong2*)(wrow);
            ulonglong2 w23 = *(const ulonglong2*)(wrow + 4);
            wrow += WSTR;

            float v0 = a0[j], v1 = a1[j], v2 = a2[j], v3 = a3[j];
            if (RELU) {
                v0 = fmaxf(v0, 0.0f); v1 = fmaxf(v1, 0.0f);
                v2 = fmaxf(v2, 0.0f); v3 = fmaxf(v3, 0.0f);
            }
            ull p0 = pack2(v0, v0), p1 = pack2(v1, v1);
            ull p2 = pack2(v2, v2), p3 = pack2(v3, v3);

            acc[0][0] = ffma2(p0, w01.x, acc[0][0]);
            acc[0][1] = ffma2(p0, w01.y, acc[0][1]);
            acc[0][2] = ffma2(p0, w23.x, acc[0][2]);
            acc[0][3] = ffma2(p0, w23.y, acc[0][3]);
            acc[1][0] = ffma2(p1, w01.x, acc[1][0]);
            acc[1][1] = ffma2(p1, w01.y, acc[1][1]);
            acc[1][2] = ffma2(p1, w23.x, acc[1][2]);
            acc[1][3] = ffma2(p1, w23.y, acc[1][3]);
            acc[2][0] = ffma2(p2, w01.x, acc[2][0]);
            acc[2][1] = ffma2(p2, w01.y, acc[2][1]);
            acc[2][2] = ffma2(p2, w23.x, acc[2][2]);
            acc[2][3] = ffma2(p2, w23.y, acc[2][3]);
            acc[3][0] = ffma2(p3, w01.x, acc[3][0]);
            acc[3][1] = ffma2(p3, w01.y, acc[3][1]);
            acc[3][2] = ffma2(p3, w23.x, acc[3][2]);
            acc[3][3] = ffma2(p3, w23.y, acc[3][3]);
        }

        #pragma unroll
        for (int k = 0; k < 4; k++) {
            float* cp = C + (s0 + k) * ldc + c0;
            #pragma unroll
            for (int i = 0; i < 4; i++) {
                float lo, hi;
                unpack2(acc[k][i], lo, hi);
                int c = c0 + 2 * i;
                if (c < NC)     { if (ACCUM) cp[2*i]   += lo; else cp[2*i]   = lo; }
                if (c + 1 < NC) { if (ACCUM) cp[2*i+1] += hi; else cp[2*i+1] = hi; }
            }
        }
    }
}

// ---------------- weight staging (k-half) ----------------
__device__ __forceinline__ void stage_res_half(float* __restrict__ ws,
                                               const float* __restrict__ Wsrc,
                                               int j0)
{
    for (int e4 = threadIdx.x; e4 < KH * H / 4; e4 += NT) {
        int j = e4 >> 5, i4 = e4 & 31;
        *(float4*)(ws + j * WSTR + i4 * 4) =
            *(const float4*)(Wsrc + (size_t)(j0 + j) * H + i4 * 4);
    }
}

// ---------------- one flow layer ----------------
__global__ void __launch_bounds__(NT, 2)
layer_kernel(const float* __restrict__ x0,
             float* __restrict__ outz,
             float* __restrict__ outld,
             int layer,
             const float* __restrict__ b_init,
             const float* __restrict__ b_res,
             const float* __restrict__ b_out)
{
    extern __shared__ float sm[];
    float* hs   = sm;                       // [TS][HS]
    float* buf2 = hs   + TS * HS;           // ts ([TS][HS]) / raw ([TS][WSTR])
    float* ws   = buf2 + TS * WSTR;         // [KH][WSTR]
    float* xs   = ws   + KH * WSTR;         // [TS][16]
    float* lds4 = xs   + TS * 16;           // [TS*3]

    const int tid = threadIdx.x;
    const int gs0 = blockIdx.x * TS;

    const float* x_in  = (layer == 0)     ? x0   : g_x;
    float*       x_out = (layer == L - 1) ? outz : g_x;

    for (int e = tid; e < TS * F; e += NT) {
        int s = e / F, f = e % F;
        xs[s * 16 + f] = x_in[(size_t)(gs0 + s) * F + (F - 1 - f)];
    }

    // ---- init GEMM: h = xs @ WiT + b_init (K=15, single pass) ----
    {
        const float* Wi = g_WiT + (size_t)layer * F * H;
        for (int e = tid; e < F * H; e += NT)
            ws[(e / H) * WSTR + (e % H)] = Wi[e];
        __syncthreads();
        gemm2<false, false, true>(xs, 16, ws, hs, HS, b_init + layer * H, F, H);
        __syncthreads();
    }

    // ---- two residual blocks (each GEMM in two k-halves) ----
    for (int blk = 0; blk < 2; blk++) {
        const float* Wa = g_WrT + ((size_t)layer * 4 + blk * 2) * H * H;
        const float* Wb = Wa + H * H;
        const float* ba = b_res + ((layer * 2 + blk) * 2 + 0) * H;
        const float* bb = b_res + ((layer * 2 + blk) * 2 + 1) * H;

        // t = relu(h) @ Wa + ba
        stage_res_half(ws, Wa, 0);
        __syncthreads();
        gemm2<true, false, true>(hs, HS, ws, buf2, HS, ba, KH, H);
        __syncthreads();
        stage_res_half(ws, Wa, KH);
        __syncthreads();
        gemm2<true, true, false>(hs + KH, HS, ws, buf2, HS, nullptr, KH, H);
        __syncthreads();

        // h += relu(t) @ Wb + bb
        stage_res_half(ws, Wb, 0);
        __syncthreads();
        gemm2<true, true, true>(buf2, HS, ws, hs, HS, bb, KH, H);
        __syncthreads();
        stage_res_half(ws, Wb, KH);
        __syncthreads();
        gemm2<true, true, false>(buf2 + KH, HS, ws, hs, HS, nullptr, KH, H);
        __syncthreads();
    }

    // ---- output GEMM + spline, 3 features (141 cols) at a time ----
    const float* Wo = g_WoT + (size_t)layer * H * FM;
    float lad_acc = 0.0f;
    const int sid  = tid / 3;
    const int flid = tid % 3;

    for (int fb = 0; fb < F; fb += 3) {
        const int base = fb * M;
        const int nc   = 3 * M;   // 141

        for (int half = 0; half < 2; half++) {
            const int j0 = half * KH;
            for (int e = tid; e < KH * WSTR; e += NT) {
                int j = e / WSTR, c = e % WSTR;
                ws[e] = (c < nc) ? Wo[(size_t)(j0 + j) * FM + base + c] : 0.0f;
            }
            __syncthreads();
            if (half == 0)
                gemm2<false, false, true>(hs, HS, ws, buf2, WSTR,
                                          b_out + (size_t)layer * FM + base, KH, nc);
            else
                gemm2<false, true, false>(hs + KH, HS, ws, buf2, WSTR,
                                          nullptr, KH, nc);
            __syncthreads();
        }

        if (tid < TS * 3) {
            const float* p = buf2 + sid * WSTR + flid * M;
            int   f  = fb + flid;
            float xv = xs[sid * 16 + f];
            float xc = fminf(fmaxf(xv, -TAIL), TAIL);
            bool inside = (xv >= -TAIL) && (xv <= TAIL);

            // widths softmax + knot walk
            float mw = -1e30f;
            #pragma unroll
            for (int i = 0; i < NB; i++) mw = fmaxf(mw, p[i]);
            float Sw = 0.0f;
            #pragma unroll
            for (int i = 0; i < NB; i++) Sw += expf(p[i] - mw);
            float invw = (1.0f - NB * MINP) / Sw;

            float cum = 0.0f;
            int   sel = 0;
            float lo = -TAIL, hi = TAIL;
            bool  gotHi = false;
            #pragma unroll
            for (int i = 0; i < NB; i++) {
                float wi = MINP + expf(p[i] - mw) * invw;
                cum += wi;
                float kv = (i == NB - 1) ? TAIL : fmaf(2.0f * TAIL, cum, -TAIL);
                if (i < NB - 1 && xc >= kv) { sel = i + 1; lo = kv; }
                if (!gotHi && xc < kv)      { hi = kv; gotHi = true; }
            }
            float w_bin = hi - lo;

            // heights softmax + knot gather
            float mh = -1e30f;
            #pragma unroll
            for (int i = 0; i < NB; i++) mh = fmaxf(mh, p[NB + i]);
            float Sh = 0.0f;
            #pragma unroll
            for (int i = 0; i < NB; i++) Sh += expf(p[NB + i] - mh);
            float invh = (1.0f - NB * MINP) / Sh;

            float cumh = 0.0f;
            float chlo = -TAIL, chhi = TAIL;
            #pragma unroll
            for (int i = 0; i < NB; i++) {
                float hv = MINP + expf(p[NB + i] - mh) * invh;
                cumh += hv;
                float kv = (i == NB - 1) ? TAIL : fmaf(2.0f * TAIL, cumh, -TAIL);
                if (i + 1 == sel)     chlo = kv;
                if (i + 1 == sel + 1) chhi = kv;
            }
            float h_bin = chhi - chlo;

            float d0 = (sel == 0)      ? 1.0f : (MINP + softplusf(p[2 * NB + sel - 1]));
            float d1 = (sel == NB - 1) ? 1.0f : (MINP + softplusf(p[2 * NB + sel]));

            float delta = h_bin / w_bin;
            float theta = (xc - lo) / w_bin;
            float omt   = 1.0f - theta;
            float tomt  = theta * omt;
            float th2   = theta * theta;
            float num   = h_bin * (delta * th2 + d0 * tomt);
            float den   = delta + (d0 + d1 - 2.0f * delta) * tomt;
            float y     = chlo + num / den;
            float dnum  = delta * delta * (d1 * th2 + 2.0f * delta * tomt + d0 * omt * omt);
            float lad   = logf(dnum) - 2.0f * logf(den);

            if (!inside) { y = xv; lad = 0.0f; }
            xs[sid * 16 + f] = y;
            lad_acc += lad;
        }
        __syncthreads();
    }

    if (tid < TS * 3) lds4[tid] = lad_acc;
    __syncthreads();

    for (int e = tid; e < TS * F; e += NT) {
        int s = e / F, f = e % F;
        x_out[(size_t)(gs0 + s) * F + f] = xs[s * 16 + f];
    }
    if (tid < TS) {
        int   g    = gs0 + tid;
        float prev = (layer == 0) ? 0.0f : g_ld[g];
        float v    = prev + lds4[tid * 3] + lds4[tid * 3 + 1] + lds4[tid * 3 + 2];
        if (layer == L - 1) outld[g] = v;
        else                g_ld[g]  = v;
    }
}

// ---------------- launch ----------------
extern "C" void kernel_launch(void* const* d_in, const int* in_sizes, int n_in,
                              void* d_out, int out_size)
{
    (void)in_sizes; (void)n_in; (void)out_size;
    const float* x  = (const float*)d_in[0];
    const float* Wi = (const float*)d_in[1];
    const float* bi = (const float*)d_in[2];
    const float* Wr = (const float*)d_in[3];
    const float* br = (const float*)d_in[4];
    const float* Wo = (const float*)d_in[5];
    const float* bo = (const float*)d_in[6];
    float* outz  = (float*)d_out;
    float* outld = (float*)d_out + (size_t)B * F;

    cudaFuncSetAttribute(layer_kernel,
                         cudaFuncAttributeMaxDynamicSharedMemorySize, SMEM_BYTES);

    premask_kernel<<<512, 256>>>(Wi, Wr, Wo);

    for (int l = 0; l < L; l++) {
        layer_kernel<<<B / TS, NT, SMEM_BYTES>>>(x, outz, outld, l, bi, br, bo);
    }
}